// round 12
// baseline (speedup 1.0000x reference)
#include <cuda_runtime.h>
#include <math.h>

#define HW 16384
#define RST 20736   // 16*16*81
#define MV 400

__device__ float g_R[64 * RST];
__device__ float g_P[64 * MV];
__device__ float g_dA[32 * MV];
__device__ float g_dB[32 * MV];

typedef unsigned long long u64t;

__device__ __forceinline__ u64t pk2(float lo, float hi) {
    u64t r;
    asm("mov.b64 %0, {%1, %2};" : "=l"(r) : "f"(lo), "f"(hi));
    return r;
}
__device__ __forceinline__ void upk2(u64t v, float& lo, float& hi) {
    asm("mov.b64 {%0, %1}, %2;" : "=f"(lo), "=f"(hi) : "l"(v));
}
__device__ __forceinline__ void fma2(u64t& d, u64t a, u64t b) {
    asm("fma.rn.f32x2 %0, %1, %2, %3;" : "=l"(d) : "l"(a), "l"(b), "l"(d));
}
__device__ __forceinline__ u64t add2(u64t a, u64t b) {
    u64t r;
    asm("add.rn.f32x2 %0, %1, %2;" : "=l"(r) : "l"(a), "l"(b));
    return r;
}

// ---------------- autocorr v4: f32x2 packed FMA, 4i x 2j register tiles ------
// CTA = (pair-block pb 0..19, sample s 0..63, strip hb 0..1), 256 thr = 8 warps.
// smem: xi 4ch x 64 x 128; xj 2 planes of 72 x 136 (4-row halo, 4-col pad, zeroed).
// Warp w: primary lag u=w (du=w-4), all dv 0..8; secondary u=8 with dv=w;
// warp 0 also (u=8, dv=8). Accumulators pack (cj0,cj1) in b64.
__global__ __launch_bounds__(256, 1) void autocorr_kernel(const float* __restrict__ x1,
                                                          const float* __restrict__ x2)
{
    extern __shared__ float sm[];
    float* xi  = sm;            // 4*8192 = 32768 floats
    float* xj0 = sm + 32768;    // 9792 floats
    float* xj1 = xj0 + 9792;    // 9792 floats
    const int s  = blockIdx.y;
    const int h0 = blockIdx.z * 64;
    const float* x = (s < 32) ? (x1 + (size_t)s * 16 * HW) : (x2 + (size_t)(s - 32) * 16 * HW);
    const int pb = blockIdx.x;
    int bi, bj;
    if (pb < 8)       { bi = 0; bj = pb; }
    else if (pb < 14) { bi = 1; bj = pb - 6; }
    else if (pb < 18) { bi = 2; bj = pb - 10; }
    else              { bi = 3; bj = pb - 12; }
    const int ibase = 4 * bi, jbase = 2 * bj;
    const int tid = threadIdx.x;

    // ---- load xi: 4 channels, rows h0..h0+63, float4 ----
    for (int k = tid; k < 8192; k += 256) {
        int ci = k >> 11, kk = k & 2047;
        ((float4*)(xi + ci * 8192))[kk] =
            ((const float4*)(x + (size_t)(ibase + ci) * HW + (size_t)h0 * 128))[kk];
    }
    // ---- load xj planes: local rows 0..71 = global h0-4..h0+67, col pad 4 ----
    for (int k = tid; k < 9792; k += 256) {
        int r = k / 136, c = k % 136;
        int g = h0 + r - 4, wg = c - 4;
        float v0 = 0.f, v1 = 0.f;
        if (g >= 0 && g < 128 && wg >= 0 && wg < 128) {
            v0 = x[(size_t)(jbase + 0) * HW + (size_t)g * 128 + wg];
            v1 = x[(size_t)(jbase + 1) * HW + (size_t)g * 128 + wg];
        }
        xj0[k] = v0; xj1[k] = v1;
    }
    __syncthreads();

    const int w = tid >> 5, lane = tid & 31, w0 = lane << 2;

    u64t acc[36];               // [ci][dv] packed (cj0,cj1)
#pragma unroll
    for (int t = 0; t < 36; t++) acc[t] = 0ull;
    u64t accs[4], acct[4];      // secondary (u=8,dv=w) and warp0 (u=8,dv=8)
#pragma unroll
    for (int t = 0; t < 4; t++) { accs[t] = 0ull; acct[t] = 0ull; }

    const float* pi  = xi + w0;
    const float* p0  = xj0 + w * 136 + w0;        // primary row h+w
    const float* p1  = xj1 + w * 136 + w0;
    const float* q0  = xj0 + 8 * 136 + w0 + w;    // secondary row h+8, col base w0+w
    const float* q1  = xj1 + 8 * 136 + w0 + w;
    const float* t0p = xj0 + 8 * 136 + w0 + 8;    // warp0 extra: col base w0+8
    const float* t1p = xj1 + 8 * 136 + w0 + 8;

#pragma unroll 1
    for (int h = 0; h < 64; h++) {
        // a operands: 4 channels x 4 w, duplicated into b64
        u64t ad[16];
#pragma unroll
        for (int ci = 0; ci < 4; ci++) {
            const float4 v = *(const float4*)(pi + ci * 8192);
            ad[ci * 4 + 0] = pk2(v.x, v.x);
            ad[ci * 4 + 1] = pk2(v.y, v.y);
            ad[ci * 4 + 2] = pk2(v.z, v.z);
            ad[ci * 4 + 3] = pk2(v.w, v.w);
        }
        // b pairs: 12 cross-plane packs from primary row
        u64t bp[12];
        {
            const float4 a0 = *(const float4*)p0;
            const float4 a1 = *(const float4*)(p0 + 4);
            const float4 a2 = *(const float4*)(p0 + 8);
            const float4 c0 = *(const float4*)p1;
            const float4 c1 = *(const float4*)(p1 + 4);
            const float4 c2 = *(const float4*)(p1 + 8);
            bp[0]  = pk2(a0.x, c0.x); bp[1]  = pk2(a0.y, c0.y);
            bp[2]  = pk2(a0.z, c0.z); bp[3]  = pk2(a0.w, c0.w);
            bp[4]  = pk2(a1.x, c1.x); bp[5]  = pk2(a1.y, c1.y);
            bp[6]  = pk2(a1.z, c1.z); bp[7]  = pk2(a1.w, c1.w);
            bp[8]  = pk2(a2.x, c2.x); bp[9]  = pk2(a2.y, c2.y);
            bp[10] = pk2(a2.z, c2.z); bp[11] = pk2(a2.w, c2.w);
        }
#pragma unroll
        for (int ci = 0; ci < 4; ci++)
#pragma unroll
            for (int dv = 0; dv < 9; dv++) {
                u64t* a = &acc[ci * 9 + dv];
                fma2(*a, ad[ci * 4 + 0], bp[dv]);
                fma2(*a, ad[ci * 4 + 1], bp[dv + 1]);
                fma2(*a, ad[ci * 4 + 2], bp[dv + 2]);
                fma2(*a, ad[ci * 4 + 3], bp[dv + 3]);
            }
        // secondary (u=8, dv=w)
        {
            u64t bs[4];
#pragma unroll
            for (int k = 0; k < 4; k++) bs[k] = pk2(q0[k], q1[k]);
#pragma unroll
            for (int ci = 0; ci < 4; ci++) {
                fma2(accs[ci], ad[ci * 4 + 0], bs[0]);
                fma2(accs[ci], ad[ci * 4 + 1], bs[1]);
                fma2(accs[ci], ad[ci * 4 + 2], bs[2]);
                fma2(accs[ci], ad[ci * 4 + 3], bs[3]);
            }
        }
        // warp 0 extra (u=8, dv=8)
        if (w == 0) {
            const float4 e0 = *(const float4*)t0p;
            const float4 e1 = *(const float4*)t1p;
            u64t bt[4] = { pk2(e0.x, e1.x), pk2(e0.y, e1.y),
                           pk2(e0.z, e1.z), pk2(e0.w, e1.w) };
#pragma unroll
            for (int ci = 0; ci < 4; ci++) {
                fma2(acct[ci], ad[ci * 4 + 0], bt[0]);
                fma2(acct[ci], ad[ci * 4 + 1], bt[1]);
                fma2(acct[ci], ad[ci * 4 + 2], bt[2]);
                fma2(acct[ci], ad[ci * 4 + 3], bt[3]);
            }
        }
        pi += 128; p0 += 136; p1 += 136; q0 += 136; q1 += 136; t0p += 136; t1p += 136;
    }

    // ---- reduce + atomic accumulate ----
    float* Rp = g_R + (size_t)s * RST;
#pragma unroll
    for (int t = 0; t < 36; t++) {
        u64t v = acc[t];
#pragma unroll
        for (int o = 16; o; o >>= 1) v = add2(v, __shfl_down_sync(0xffffffffu, v, o));
        if (lane == 0) {
            float v0, v1; upk2(v, v0, v1);
            const int i = ibase + t / 9, dv = t % 9;
#pragma unroll
            for (int cj = 0; cj < 2; cj++) {
                const int j = jbase + cj;
                const float vv = cj ? v1 : v0;
                if (i < j) {
                    atomicAdd(&Rp[(i * 16 + j) * 81 + w * 9 + dv], vv);
                    atomicAdd(&Rp[(j * 16 + i) * 81 + (8 - w) * 9 + (8 - dv)], vv);
                } else if (i == j) {
                    atomicAdd(&Rp[(i * 16 + j) * 81 + w * 9 + dv], vv);
                }
            }
        }
    }
#pragma unroll
    for (int t = 0; t < 4; t++) {
        u64t v = accs[t];
#pragma unroll
        for (int o = 16; o; o >>= 1) v = add2(v, __shfl_down_sync(0xffffffffu, v, o));
        if (lane == 0) {
            float v0, v1; upk2(v, v0, v1);
            const int i = ibase + t, dv = w;  // u = 8
#pragma unroll
            for (int cj = 0; cj < 2; cj++) {
                const int j = jbase + cj;
                const float vv = cj ? v1 : v0;
                if (i < j) {
                    atomicAdd(&Rp[(i * 16 + j) * 81 + 8 * 9 + dv], vv);
                    atomicAdd(&Rp[(j * 16 + i) * 81 + 0 * 9 + (8 - dv)], vv);
                } else if (i == j) {
                    atomicAdd(&Rp[(i * 16 + j) * 81 + 8 * 9 + dv], vv);
                }
            }
        }
    }
    if (w == 0) {
#pragma unroll
        for (int t = 0; t < 4; t++) {
            u64t v = acct[t];
#pragma unroll
            for (int o = 16; o; o >>= 1) v = add2(v, __shfl_down_sync(0xffffffffu, v, o));
            if (lane == 0) {
                float v0, v1; upk2(v, v0, v1);
                const int i = ibase + t;  // u = 8, dv = 8
#pragma unroll
                for (int cj = 0; cj < 2; cj++) {
                    const int j = jbase + cj;
                    const float vv = cj ? v1 : v0;
                    if (i < j) {
                        atomicAdd(&Rp[(i * 16 + j) * 81 + 8 * 9 + 8], vv);
                        atomicAdd(&Rp[(j * 16 + i) * 81 + 0], vv);
                    } else if (i == j) {
                        atomicAdd(&Rp[(i * 16 + j) * 81 + 8 * 9 + 8], vv);
                    }
                }
            }
        }
    }
}

// ---------------- crosscorr: CTA = (channel j, sample s) ---------------------
__global__ __launch_bounds__(160) void crosscorr_kernel(const float* __restrict__ x1,
                                                        const float* __restrict__ x2,
                                                        const float* __restrict__ y1,
                                                        const float* __restrict__ y2)
{
    extern __shared__ float sm[];
    float* ys = sm;
    float* xs = sm + 16384;
    const int s = blockIdx.y, j = blockIdx.x;
    const float* x = (s < 32) ? (x1 + (size_t)s * 16 * HW) : (x2 + (size_t)(s - 32) * 16 * HW);
    const float* y = (s < 32) ? (y1 + (size_t)s * HW) : (y2 + (size_t)(s - 32) * HW);
    const int tid = threadIdx.x;
    {
        for (int k = tid; k < HW / 4; k += 160) ((float4*)ys)[k] = ((const float4*)y)[k];
        const float* gx = x + (size_t)j * HW;
        for (int k = tid; k < 128 * 34; k += 160) {
            int r = k / 34, w0 = (k % 34) * 4 - 4;
            float t0 = (w0 >= 0 && w0 < 128)         ? gx[r * 128 + w0]     : 0.f;
            float t1 = (w0 + 1 >= 0 && w0 + 1 < 128) ? gx[r * 128 + w0 + 1] : 0.f;
            float t2 = (w0 + 2 >= 0 && w0 + 2 < 128) ? gx[r * 128 + w0 + 2] : 0.f;
            float t3 = (w0 + 3 >= 0 && w0 + 3 < 128) ? gx[r * 128 + w0 + 3] : 0.f;
            ((float4*)xs)[k] = make_float4(t0, t1, t2, t3);
        }
    }
    __syncthreads();
    const int warp = tid >> 5, lane = tid & 31;
    const int du = warp - 2, w0 = lane << 2;
    float acc[5] = {0.f, 0.f, 0.f, 0.f, 0.f};
    const int hbeg = (du < 0) ? -du : 0;
    const int hend = (du > 0) ? 128 - du : 128;
    const float* py = ys + hbeg * 128 + w0;
    const float* px = xs + (hbeg + du) * 136 + w0;
    for (int h = hbeg; h < hend; h++) {
        const float4 av = *(const float4*)py;
        const float4 b0 = *(const float4*)px;
        const float4 b1 = *(const float4*)(px + 4);
        const float4 b2 = *(const float4*)(px + 8);
        const float bb[12] = { b0.x, b0.y, b0.z, b0.w, b1.x, b1.y, b1.z, b1.w,
                               b2.x, b2.y, b2.z, b2.w };
#pragma unroll
        for (int t = 0; t < 5; t++) {
            acc[t] = fmaf(av.x, bb[t + 2], acc[t]);
            acc[t] = fmaf(av.y, bb[t + 3], acc[t]);
            acc[t] = fmaf(av.z, bb[t + 4], acc[t]);
            acc[t] = fmaf(av.w, bb[t + 5], acc[t]);
        }
        py += 128; px += 136;
    }
#pragma unroll
    for (int t = 0; t < 5; t++) {
        float v = acc[t];
#pragma unroll
        for (int o = 16; o; o >>= 1) v += __shfl_down_sync(0xffffffffu, v, o);
        if (lane == 0) g_P[(size_t)s * MV + j * 25 + warp * 5 + t] = v;
    }
}

// ---------------- CG solve from R (Q never materialized) ---------------------
__device__ __forceinline__ float dot400(const float* A, const float* B, float* scr, int t)
{
    float v = 0.f;
    for (int k = t; k < MV; k += 256) v += A[k] * B[k];
#pragma unroll
    for (int o = 16; o; o >>= 1) v += __shfl_down_sync(0xffffffffu, v, o);
    if ((t & 31) == 0) scr[t >> 5] = v;
    __syncthreads();
    if (t < 32) {
        float w = (t < 8) ? scr[t] : 0.f;
#pragma unroll
        for (int o = 4; o; o >>= 1) w += __shfl_down_sync(0xffffffffu, w, o);
        if (t == 0) scr[0] = w;
    }
    __syncthreads();
    float r = scr[0];
    __syncthreads();
    return r;
}

__global__ __launch_bounds__(256) void cg_kernel(int soff, const float* __restrict__ dprev,
                                                 const float* __restrict__ alpha,
                                                 const float* __restrict__ reg,
                                                 float* __restrict__ dout)
{
    extern __shared__ float sm[];
    float* Rs  = sm;                 // 20736
    float* red = Rs + RST;           // 16*400
    float* vx  = red + 16 * MV;      // 400
    float* vr  = vx + MV;
    float* vp  = vr + MV;
    float* vq  = vp + MV;
    float* scr = vq + MV;            // 256
    const int s = blockIdx.x, t = threadIdx.x;
    const float a = alpha[s] * 16384.f * reg[0] / 400.f;

    {
        const float4* gr = (const float4*)(g_R + (size_t)(s + soff) * RST);
        for (int k = t; k < RST / 4; k += 256) ((float4*)Rs)[k] = gr[k];
    }
    for (int k = t; k < MV; k += 256) {
        float b = g_P[(size_t)(s + soff) * MV + k] + a * dprev[(size_t)s * MV + k];
        vr[k] = b; vp[k] = b; vx[k] = 0.f;
    }
    __syncthreads();
    float rs = dot400(vr, vr, scr, t);

    const int jj = t & 15;
    const float* Rb = Rs + t * 81;   // block (i = t>>4, j = t&15)

    for (int it = 0; it < 14; it++) {
        float vj[25];
#pragma unroll
        for (int o = 0; o < 25; o++) vj[o] = vp[jj * 25 + o];
        float acc[25];
#pragma unroll
        for (int o = 0; o < 25; o++) acc[o] = 0.f;
#pragma unroll
        for (int oi = 0; oi < 5; oi++)
#pragma unroll
            for (int oj = 0; oj < 5; oj++) {
                const float v = vj[oi * 5 + oj];
#pragma unroll
                for (int p = 0; p < 5; p++)
#pragma unroll
                    for (int q = 0; q < 5; q++)
                        acc[p * 5 + q] = fmaf(Rb[(4 + oi - p) * 9 + (4 + oj - q)], v, acc[p * 5 + q]);
            }
#pragma unroll
        for (int o = 0; o < 25; o++) red[jj * MV + (t >> 4) * 25 + o] = acc[o];
        __syncthreads();
        for (int k = t; k < MV; k += 256) {
            float ssum = a * vp[k];
#pragma unroll
            for (int j2 = 0; j2 < 16; j2++) ssum += red[j2 * MV + k];
            vq[k] = ssum;
        }
        __syncthreads();
        float pq = dot400(vp, vq, scr, t);
        float al = rs / pq;
        for (int k = t; k < MV; k += 256) { vx[k] += al * vp[k]; vr[k] -= al * vq[k]; }
        __syncthreads();
        float rs2 = dot400(vr, vr, scr, t);
        float be = rs2 / rs;
        rs = rs2;
        for (int k = t; k < MV; k += 256) vp[k] = vr[k] + be * vp[k];
        __syncthreads();
    }
    for (int k = t; k < MV; k += 256) dout[(size_t)s * MV + k] = vx[k];
}

// ---------------- conv head: 6 x conv3x3(pad1) on 5x5 maps -------------------
__device__ __forceinline__ void conv5(float* outb, const float* inb, const float* w,
                                      const float* bias, int cin, int doRelu, int t)
{
    if (t < MV) {
        const int oc = t / 25, pos = t % 25, p = pos / 5, q = pos % 5;
        float v = bias[oc];
        for (int ic = 0; ic < cin; ic++) {
            const float* wp = w + (oc * cin + ic) * 9;
            const float* ip = inb + ic * 25;
#pragma unroll
            for (int kh = 0; kh < 3; kh++) {
                int r = p + kh - 1;
                if (r < 0 || r > 4) continue;
#pragma unroll
                for (int kw = 0; kw < 3; kw++) {
                    int c = q + kw - 1;
                    if (c < 0 || c > 4) continue;
                    v = fmaf(wp[kh * 3 + kw], ip[r * 5 + c], v);
                }
            }
        }
        outb[t] = doRelu ? fmaxf(v, 0.f) : v;
    }
    __syncthreads();
}

__global__ __launch_bounds__(400) void head_kernel(const float* __restrict__ beta,
    const float* w1, const float* b1, const float* w2, const float* b2,
    const float* w3, const float* b3, const float* w4, const float* b4,
    const float* w5, const float* b5, const float* w6, const float* b6,
    float* __restrict__ out)
{
    __shared__ float h0[17 * 25], bA[16 * 25], bB[16 * 25];
    const int s = blockIdx.x, t = threadIdx.x;
    if (t < MV) h0[t] = g_dB[(size_t)s * MV + t];
    if (t < 25) h0[MV + t] = 1.0f / sqrtf(beta[s]);
    __syncthreads();
    conv5(bA, h0, w1, b1, 17, 1, t);
    conv5(bB, bA, w2, b2, 16, 1, t);
    conv5(bA, bB, w3, b3, 16, 1, t);
    conv5(bB, bA, w4, b4, 16, 1, t);
    conv5(bA, bB, w5, b5, 16, 1, t);
    if (t < MV) {
        const int oc = t / 25, pos = t % 25, p = pos / 5, q = pos % 5;
        float v = b6[oc];
        for (int ic = 0; ic < 16; ic++) {
            const float* wp = w6 + (oc * 16 + ic) * 9;
            const float* ip = bA + ic * 25;
#pragma unroll
            for (int kh = 0; kh < 3; kh++) {
                int r = p + kh - 1;
                if (r < 0 || r > 4) continue;
#pragma unroll
                for (int kw = 0; kw < 3; kw++) {
                    int c = q + kw - 1;
                    if (c < 0 || c > 4) continue;
                    v = fmaf(wp[kh * 3 + kw], ip[r * 5 + c], v);
                }
            }
        }
        out[(size_t)s * MV + t] = v + h0[t];
    }
}

extern "C" void kernel_launch(void* const* d_in, const int* in_sizes, int n_in,
                              void* d_out, int out_size)
{
    const float* x1 = (const float*)d_in[0];
    const float* x2 = (const float*)d_in[1];
    const float* d  = (const float*)d_in[2];
    const float* y1 = (const float*)d_in[3];
    const float* y2 = (const float*)d_in[4];
    const float* alpha = (const float*)d_in[5];
    const float* beta  = (const float*)d_in[6];
    const float* reg   = (const float*)d_in[7];
    const float* w1 = (const float*)d_in[8];  const float* b1 = (const float*)d_in[9];
    const float* w2 = (const float*)d_in[10]; const float* b2 = (const float*)d_in[11];
    const float* w3 = (const float*)d_in[12]; const float* b3 = (const float*)d_in[13];
    const float* w4 = (const float*)d_in[14]; const float* b4 = (const float*)d_in[15];
    const float* w5 = (const float*)d_in[16]; const float* b5 = (const float*)d_in[17];
    const float* w6 = (const float*)d_in[18]; const float* b6 = (const float*)d_in[19];

    const int SM_AC = (32768 + 2 * 9792) * 4;              // 209,408 B
    const int SM_CC = 33792 * 4;                           // 135,168 B
    const int SM_CG = (RST + 16 * MV + 4 * MV + 256) * 4;  // ~115 KB

    cudaFuncSetAttribute(autocorr_kernel,  cudaFuncAttributeMaxDynamicSharedMemorySize, SM_AC);
    cudaFuncSetAttribute(crosscorr_kernel, cudaFuncAttributeMaxDynamicSharedMemorySize, SM_CC);
    cudaFuncSetAttribute(cg_kernel,        cudaFuncAttributeMaxDynamicSharedMemorySize, SM_CG);

    float* dA; cudaGetSymbolAddress((void**)&dA, g_dA);
    float* dB; cudaGetSymbolAddress((void**)&dB, g_dB);
    float* Rz; cudaGetSymbolAddress((void**)&Rz, g_R);

    cudaMemsetAsync(Rz, 0, (size_t)64 * RST * sizeof(float));
    dim3 ga(20, 64, 2);
    autocorr_kernel<<<ga, 256, SM_AC>>>(x1, x2);
    dim3 gc(16, 64);
    crosscorr_kernel<<<gc, 160, SM_CC>>>(x1, x2, y1, y2);
    cg_kernel<<<32, 256, SM_CG>>>(0, d, alpha, reg, dA);
    cg_kernel<<<32, 256, SM_CG>>>(32, dA, alpha, reg, dB);
    head_kernel<<<32, 400>>>(beta, w1, b1, w2, b2, w3, b3, w4, b4, w5, b5, w6, b6,
                             (float*)d_out);
}

// round 14
// speedup vs baseline: 1.0537x; 1.0537x over previous
#include <cuda_runtime.h>
#include <cuda_bf16.h>
#include <mma.h>
#include <math.h>
#include <stdint.h>

using namespace nvcuda;

#define HW  16384
#define RST 20736           // 16*16*81
#define MV  400
#define GDS (128*144)

__device__ float g_R[64 * RST];
__device__ float g_P[64 * MV];
__device__ float g_dA[32 * MV];
__device__ float g_dB[32 * MV];
__device__ float g_D[4 * 64 * GDS];   // [strip][s][128][144], 18.9 MB

__device__ __forceinline__ uint32_t pkb(float a, float b) {
    __nv_bfloat162 t(__float2bfloat16(a), __float2bfloat16(b));
    return *reinterpret_cast<uint32_t*>(&t);
}
__device__ __forceinline__ void split8(const float* f, uint32_t* hh, uint32_t* ll) {
#pragma unroll
    for (int q = 0; q < 4; q++) {
        float a = f[2 * q], b = f[2 * q + 1];
        __nv_bfloat16 ha = __float2bfloat16(a), hb = __float2bfloat16(b);
        float la = a - __bfloat162float(ha), lb = b - __bfloat162float(hb);
        __nv_bfloat162 th(ha, hb), tl(__float2bfloat16(la), __float2bfloat16(lb));
        hh[q] = *reinterpret_cast<uint32_t*>(&th);
        ll[q] = *reinterpret_cast<uint32_t*>(&tl);
    }
}

// ---------------- autocorr GEMM via wmma bf16 (HMMA path) --------------------
// CTA = (strip 0..3, sample 0..63). D[u*16+i][v*16+j] += over g in strip of
//   sum_w x_i[g+4-u, w] * x_j[g, w+v-4]   (u 0..7, v 0..8)
__global__ __launch_bounds__(256) void gemm_kernel(const float* __restrict__ x1,
                                                   const float* __restrict__ x2)
{
    __shared__ __align__(16) __nv_bfloat16 Ahi[128 * 16], Alo[128 * 16];
    __shared__ __align__(16) __nv_bfloat16 Bhi[144 * 16], Blo[144 * 16];

    const int s = blockIdx.y, strip = blockIdx.x;
    const float* x = (s < 32) ? x1 + (size_t)s * 16 * HW
                              : x2 + (size_t)(s - 32) * 16 * HW;
    const int tid = threadIdx.x;
    const int wu = tid >> 5;              // warp id = u tile (0..7)

    wmma::fragment<wmma::accumulator, 16, 16, 16, float> acc[9];
#pragma unroll
    for (int t = 0; t < 9; t++) wmma::fill_fragment(acc[t], 0.0f);

    const int ma = tid >> 1;              // A staging: row m
    const int ka8 = (tid & 1) * 8;        // A staging: k offset
    const int u_s = ma >> 4, i_s = ma & 15;

    for (int gs = 0; gs < 32; gs++) {
        const int g = strip * 32 + gs;
        for (int wc = 0; wc < 8; wc++) {
            const int w = wc * 16;
            // ---- stage A[m][16]: x_i[g+4-u, w+kk], zero out-of-range rows ----
            {
                const int h = g + 4 - u_s;
                float f[8];
                if (h >= 0 && h < 128) {
                    const float* p = x + (size_t)i_s * HW + (size_t)h * 128 + w + ka8;
                    float4 v0 = *(const float4*)p, v1 = *(const float4*)(p + 4);
                    f[0] = v0.x; f[1] = v0.y; f[2] = v0.z; f[3] = v0.w;
                    f[4] = v1.x; f[5] = v1.y; f[6] = v1.z; f[7] = v1.w;
                } else {
#pragma unroll
                    for (int q = 0; q < 8; q++) f[q] = 0.f;
                }
                uint32_t hh[4], ll[4];
                split8(f, hh, ll);
                *(uint4*)&Ahi[ma * 16 + ka8] = make_uint4(hh[0], hh[1], hh[2], hh[3]);
                *(uint4*)&Alo[ma * 16 + ka8] = make_uint4(ll[0], ll[1], ll[2], ll[3]);
            }
            // ---- stage B[n][16]: x_j[g, w+kk+v-4], zero out-of-range cols ----
            for (int idx = tid; idx < 288; idx += 256) {
                const int n = idx >> 1, k8 = (idx & 1) * 8;
                const int j = n & 15, v = n >> 4;
                const float* row = x + (size_t)j * HW + (size_t)g * 128;
                float f[8];
#pragma unroll
                for (int q = 0; q < 8; q++) {
                    int c = w + k8 + q + v - 4;
                    f[q] = (c >= 0 && c < 128) ? row[c] : 0.f;
                }
                uint32_t hh[4], ll[4];
                split8(f, hh, ll);
                *(uint4*)&Bhi[n * 16 + k8] = make_uint4(hh[0], hh[1], hh[2], hh[3]);
                *(uint4*)&Blo[n * 16 + k8] = make_uint4(ll[0], ll[1], ll[2], ll[3]);
            }
            __syncthreads();

            wmma::fragment<wmma::matrix_a, 16, 16, 16, __nv_bfloat16, wmma::row_major> af;
            wmma::fragment<wmma::matrix_b, 16, 16, 16, __nv_bfloat16, wmma::col_major> bf;
            // pass 1+2: A=hi with B=hi then B=lo
            wmma::load_matrix_sync(af, Ahi + wu * 256, 16);
#pragma unroll
            for (int tn = 0; tn < 9; tn++) {
                wmma::load_matrix_sync(bf, Bhi + tn * 256, 16);
                wmma::mma_sync(acc[tn], af, bf, acc[tn]);
            }
#pragma unroll
            for (int tn = 0; tn < 9; tn++) {
                wmma::load_matrix_sync(bf, Blo + tn * 256, 16);
                wmma::mma_sync(acc[tn], af, bf, acc[tn]);
            }
            // pass 3: A=lo, B=hi
            wmma::load_matrix_sync(af, Alo + wu * 256, 16);
#pragma unroll
            for (int tn = 0; tn < 9; tn++) {
                wmma::load_matrix_sync(bf, Bhi + tn * 256, 16);
                wmma::mma_sync(acc[tn], af, bf, acc[tn]);
            }
            __syncthreads();
        }
    }

    float* dst = g_D + ((size_t)strip * 64 + s) * GDS;
#pragma unroll
    for (int tn = 0; tn < 9; tn++)
        wmma::store_matrix_sync(dst + wu * 16 * 144 + tn * 16, acc[tn], 144,
                                wmma::mem_row_major);
}

// ---------------- fill: sum 4 strip-partials -> g_R, mirror u=8 --------------
__global__ __launch_bounds__(256) void fill_kernel()
{
    const int s = blockIdx.x, t = threadIdx.x;
    for (int idx = t; idx < RST; idx += 256) {
        const int pair = idx / 81, lag = idx - pair * 81;
        const int i = pair >> 4, j = pair & 15, u = lag / 9, v = lag - u * 9;
        int m, n;
        if (u < 8) { m = u * 16 + i; n = v * 16 + j; }
        else       { m = j;          n = (8 - v) * 16 + i; }  // R[i,j,8,v]=R[j,i,0,8-v]
        float a = 0.f;
#pragma unroll
        for (int st = 0; st < 4; st++)
            a += g_D[((size_t)st * 64 + s) * GDS + m * 144 + n];
        g_R[(size_t)s * RST + idx] = a;
    }
}

// ---------------- crosscorr: CTA = (channel j, sample s) ---------------------
__global__ __launch_bounds__(160) void crosscorr_kernel(const float* __restrict__ x1,
                                                        const float* __restrict__ x2,
                                                        const float* __restrict__ y1,
                                                        const float* __restrict__ y2)
{
    extern __shared__ float sm[];
    float* ys = sm;
    float* xs = sm + 16384;
    const int s = blockIdx.y, j = blockIdx.x;
    const float* x = (s < 32) ? (x1 + (size_t)s * 16 * HW) : (x2 + (size_t)(s - 32) * 16 * HW);
    const float* y = (s < 32) ? (y1 + (size_t)s * HW) : (y2 + (size_t)(s - 32) * HW);
    const int tid = threadIdx.x;
    {
        for (int k = tid; k < HW / 4; k += 160) ((float4*)ys)[k] = ((const float4*)y)[k];
        const float* gx = x + (size_t)j * HW;
        for (int k = tid; k < 128 * 34; k += 160) {
            int r = k / 34, w0 = (k % 34) * 4 - 4;
            float t0 = (w0 >= 0 && w0 < 128)         ? gx[r * 128 + w0]     : 0.f;
            float t1 = (w0 + 1 >= 0 && w0 + 1 < 128) ? gx[r * 128 + w0 + 1] : 0.f;
            float t2 = (w0 + 2 >= 0 && w0 + 2 < 128) ? gx[r * 128 + w0 + 2] : 0.f;
            float t3 = (w0 + 3 >= 0 && w0 + 3 < 128) ? gx[r * 128 + w0 + 3] : 0.f;
            ((float4*)xs)[k] = make_float4(t0, t1, t2, t3);
        }
    }
    __syncthreads();
    const int warp = tid >> 5, lane = tid & 31;
    const int du = warp - 2, w0 = lane << 2;
    float acc[5] = {0.f, 0.f, 0.f, 0.f, 0.f};
    const int hbeg = (du < 0) ? -du : 0;
    const int hend = (du > 0) ? 128 - du : 128;
    const float* py = ys + hbeg * 128 + w0;
    const float* px = xs + (hbeg + du) * 136 + w0;
    for (int h = hbeg; h < hend; h++) {
        const float4 av = *(const float4*)py;
        const float4 b0 = *(const float4*)px;
        const float4 b1 = *(const float4*)(px + 4);
        const float4 b2 = *(const float4*)(px + 8);
        const float bb[12] = { b0.x, b0.y, b0.z, b0.w, b1.x, b1.y, b1.z, b1.w,
                               b2.x, b2.y, b2.z, b2.w };
#pragma unroll
        for (int t = 0; t < 5; t++) {
            acc[t] = fmaf(av.x, bb[t + 2], acc[t]);
            acc[t] = fmaf(av.y, bb[t + 3], acc[t]);
            acc[t] = fmaf(av.z, bb[t + 4], acc[t]);
            acc[t] = fmaf(av.w, bb[t + 5], acc[t]);
        }
        py += 128; px += 136;
    }
#pragma unroll
    for (int t = 0; t < 5; t++) {
        float v = acc[t];
#pragma unroll
        for (int o = 16; o; o >>= 1) v += __shfl_down_sync(0xffffffffu, v, o);
        if (lane == 0) g_P[(size_t)s * MV + j * 25 + warp * 5 + t] = v;
    }
}

// ---------------- CG solve from R (Q never materialized) ---------------------
__device__ __forceinline__ float dot400(const float* A, const float* B, float* scr, int t)
{
    float v = 0.f;
    for (int k = t; k < MV; k += 256) v += A[k] * B[k];
#pragma unroll
    for (int o = 16; o; o >>= 1) v += __shfl_down_sync(0xffffffffu, v, o);
    if ((t & 31) == 0) scr[t >> 5] = v;
    __syncthreads();
    if (t < 32) {
        float w = (t < 8) ? scr[t] : 0.f;
#pragma unroll
        for (int o = 4; o; o >>= 1) w += __shfl_down_sync(0xffffffffu, w, o);
        if (t == 0) scr[0] = w;
    }
    __syncthreads();
    float r = scr[0];
    __syncthreads();
    return r;
}

__global__ __launch_bounds__(256) void cg_kernel(int soff, const float* __restrict__ dprev,
                                                 const float* __restrict__ alpha,
                                                 const float* __restrict__ reg,
                                                 float* __restrict__ dout)
{
    extern __shared__ float sm[];
    float* Rs  = sm;
    float* red = Rs + RST;
    float* vx  = red + 16 * MV;
    float* vr  = vx + MV;
    float* vp  = vr + MV;
    float* vq  = vp + MV;
    float* scr = vq + MV;
    const int s = blockIdx.x, t = threadIdx.x;
    const float a = alpha[s] * 16384.f * reg[0] / 400.f;

    {
        const float4* gr = (const float4*)(g_R + (size_t)(s + soff) * RST);
        for (int k = t; k < RST / 4; k += 256) ((float4*)Rs)[k] = gr[k];
    }
    for (int k = t; k < MV; k += 256) {
        float b = g_P[(size_t)(s + soff) * MV + k] + a * dprev[(size_t)s * MV + k];
        vr[k] = b; vp[k] = b; vx[k] = 0.f;
    }
    __syncthreads();
    float rs = dot400(vr, vr, scr, t);

    const int jj = t & 15;
    const float* Rb = Rs + t * 81;

    for (int it = 0; it < 14; it++) {
        float vj[25];
#pragma unroll
        for (int o = 0; o < 25; o++) vj[o] = vp[jj * 25 + o];
        float acc[25];
#pragma unroll
        for (int o = 0; o < 25; o++) acc[o] = 0.f;
#pragma unroll
        for (int oi = 0; oi < 5; oi++)
#pragma unroll
            for (int oj = 0; oj < 5; oj++) {
                const float v = vj[oi * 5 + oj];
#pragma unroll
                for (int p = 0; p < 5; p++)
#pragma unroll
                    for (int q = 0; q < 5; q++)
                        acc[p * 5 + q] = fmaf(Rb[(4 + oi - p) * 9 + (4 + oj - q)], v, acc[p * 5 + q]);
            }
#pragma unroll
        for (int o = 0; o < 25; o++) red[jj * MV + (t >> 4) * 25 + o] = acc[o];
        __syncthreads();
        for (int k = t; k < MV; k += 256) {
            float ssum = a * vp[k];
#pragma unroll
            for (int j2 = 0; j2 < 16; j2++) ssum += red[j2 * MV + k];
            vq[k] = ssum;
        }
        __syncthreads();
        float pq = dot400(vp, vq, scr, t);
        float al = rs / pq;
        for (int k = t; k < MV; k += 256) { vx[k] += al * vp[k]; vr[k] -= al * vq[k]; }
        __syncthreads();
        float rs2 = dot400(vr, vr, scr, t);
        float be = rs2 / rs;
        rs = rs2;
        for (int k = t; k < MV; k += 256) vp[k] = vr[k] + be * vp[k];
        __syncthreads();
    }
    for (int k = t; k < MV; k += 256) dout[(size_t)s * MV + k] = vx[k];
}

// ---------------- conv head: 6 x conv3x3(pad1) on 5x5 maps -------------------
__device__ __forceinline__ void conv5(float* outb, const float* inb, const float* w,
                                      const float* bias, int cin, int doRelu, int t)
{
    if (t < MV) {
        const int oc = t / 25, pos = t % 25, p = pos / 5, q = pos % 5;
        float v = bias[oc];
        for (int ic = 0; ic < cin; ic++) {
            const float* wp = w + (oc * cin + ic) * 9;
            const float* ip = inb + ic * 25;
#pragma unroll
            for (int kh = 0; kh < 3; kh++) {
                int r = p + kh - 1;
                if (r < 0 || r > 4) continue;
#pragma unroll
                for (int kw = 0; kw < 3; kw++) {
                    int c = q + kw - 1;
                    if (c < 0 || c > 4) continue;
                    v = fmaf(wp[kh * 3 + kw], ip[r * 5 + c], v);
                }
            }
        }
        outb[t] = doRelu ? fmaxf(v, 0.f) : v;
    }
    __syncthreads();
}

__global__ __launch_bounds__(400) void head_kernel(const float* __restrict__ beta,
    const float* w1, const float* b1, const float* w2, const float* b2,
    const float* w3, const float* b3, const float* w4, const float* b4,
    const float* w5, const float* b5, const float* w6, const float* b6,
    float* __restrict__ out)
{
    __shared__ float h0[17 * 25], bA[16 * 25], bB[16 * 25];
    const int s = blockIdx.x, t = threadIdx.x;
    if (t < MV) h0[t] = g_dB[(size_t)s * MV + t];
    if (t < 25) h0[MV + t] = 1.0f / sqrtf(beta[s]);
    __syncthreads();
    conv5(bA, h0, w1, b1, 17, 1, t);
    conv5(bB, bA, w2, b2, 16, 1, t);
    conv5(bA, bB, w3, b3, 16, 1, t);
    conv5(bB, bA, w4, b4, 16, 1, t);
    conv5(bA, bB, w5, b5, 16, 1, t);
    if (t < MV) {
        const int oc = t / 25, pos = t % 25, p = pos / 5, q = pos % 5;
        float v = b6[oc];
        for (int ic = 0; ic < 16; ic++) {
            const float* wp = w6 + (oc * 16 + ic) * 9;
            const float* ip = bA + ic * 25;
#pragma unroll
            for (int kh = 0; kh < 3; kh++) {
                int r = p + kh - 1;
                if (r < 0 || r > 4) continue;
#pragma unroll
                for (int kw = 0; kw < 3; kw++) {
                    int c = q + kw - 1;
                    if (c < 0 || c > 4) continue;
                    v = fmaf(wp[kh * 3 + kw], ip[r * 5 + c], v);
                }
            }
        }
        out[(size_t)s * MV + t] = v + h0[t];
    }
}

extern "C" void kernel_launch(void* const* d_in, const int* in_sizes, int n_in,
                              void* d_out, int out_size)
{
    const float* x1 = (const float*)d_in[0];
    const float* x2 = (const float*)d_in[1];
    const float* d  = (const float*)d_in[2];
    const float* y1 = (const float*)d_in[3];
    const float* y2 = (const float*)d_in[4];
    const float* alpha = (const float*)d_in[5];
    const float* beta  = (const float*)d_in[6];
    const float* reg   = (const float*)d_in[7];
    const float* w1 = (const float*)d_in[8];  const float* b1 = (const float*)d_in[9];
    const float* w2 = (const float*)d_in[10]; const float* b2 = (const float*)d_in[11];
    const float* w3 = (const float*)d_in[12]; const float* b3 = (const float*)d_in[13];
    const float* w4 = (const float*)d_in[14]; const float* b4 = (const float*)d_in[15];
    const float* w5 = (const float*)d_in[16]; const float* b5 = (const float*)d_in[17];
    const float* w6 = (const float*)d_in[18]; const float* b6 = (const float*)d_in[19];

    const int SM_CC = 33792 * 4;
    const int SM_CG = (RST + 16 * MV + 4 * MV + 256) * 4;

    cudaFuncSetAttribute(crosscorr_kernel, cudaFuncAttributeMaxDynamicSharedMemorySize, SM_CC);
    cudaFuncSetAttribute(cg_kernel,        cudaFuncAttributeMaxDynamicSharedMemorySize, SM_CG);

    float* dA; cudaGetSymbolAddress((void**)&dA, g_dA);
    float* dB; cudaGetSymbolAddress((void**)&dB, g_dB);

    dim3 gg(4, 64);
    gemm_kernel<<<gg, 256>>>(x1, x2);
    dim3 gc(16, 64);
    crosscorr_kernel<<<gc, 160, SM_CC>>>(x1, x2, y1, y2);
    fill_kernel<<<64, 256>>>();
    cg_kernel<<<32, 256, SM_CG>>>(0, d, alpha, reg, dA);
    cg_kernel<<<32, 256, SM_CG>>>(32, dA, alpha, reg, dB);
    head_kernel<<<32, 400>>>(beta, w1, b1, w2, b2, w3, b3, w4, b4, w5, b5, w6, b6,
                             (float*)d_out);
}